// round 13
// baseline (speedup 1.0000x reference)
#include <cuda_runtime.h>
#include <cuda_fp16.h>
#include <cstdint>

// Static problem shapes (from setup_inputs)
constexpr int kS   = 2;
constexpr int kVin = 3;
constexpr int kVt  = 4;
constexpr int kC   = 16;
constexpr int kD   = 64;
constexpr int kH   = 96;
constexpr int kW   = 96;
constexpr int kHlo = 48;
constexpr int kWlo = 48;

constexpr int kDHW  = kD * kH * kW;           // 589824
constexpr int kNVox = kS * kVin * kDHW;       // 3,538,944
constexpr int kRays = kS * kVt * kHlo * kWlo; // 18432

// Scratch: channel-last fp16 volume (113 MB), pre-scaled by 1/3
__device__ __half g_encT[(size_t)kNVox * kC];
__device__ float  g_rlo[kS * kVt * kC * kHlo * kWlo];

// ---------------- packed f32x2 helpers (sm_103a) ----------------
using u64 = unsigned long long;
__device__ __forceinline__ u64 pack2(float lo, float hi) {
    u64 r; asm("mov.b64 %0,{%1,%2};" : "=l"(r) : "f"(lo), "f"(hi)); return r;
}
__device__ __forceinline__ float2 unpack2(u64 v) {
    float2 f; asm("mov.b64 {%0,%1},%2;" : "=f"(f.x), "=f"(f.y) : "l"(v)); return f;
}
__device__ __forceinline__ u64 ffma2(u64 a, u64 b, u64 c) {
    u64 d; asm("fma.rn.f32x2 %0,%1,%2,%3;" : "=l"(d) : "l"(a), "l"(b), "l"(c)); return d;
}
__device__ __forceinline__ u64 h2f2p(unsigned u) {
    __half2 h = *reinterpret_cast<__half2*>(&u);
    float2 f = __half22float2(h);
    return pack2(f.x, f.y);
}

// ---------------- mma.sync m16n8k16 helper (tensor pipe) ----------------
__device__ __forceinline__ void mma16816(float& c0, float& c1, float& c2, float& c3,
                                         uint32_t a0, uint32_t a1, uint32_t a2, uint32_t a3,
                                         uint32_t b0, uint32_t b1) {
    asm volatile(
        "mma.sync.aligned.m16n8k16.row.col.f32.f16.f16.f32 "
        "{%0,%1,%2,%3}, {%4,%5,%6,%7}, {%8,%9}, {%0,%1,%2,%3};"
        : "+f"(c0), "+f"(c1), "+f"(c2), "+f"(c3)
        : "r"(a0), "r"(a1), "r"(a2), "r"(a3), "r"(b0), "r"(b1));
}
__device__ __forceinline__ uint32_t packrelu(float x, float y, float bx, float by) {
    __half2 h = __floats2half2_rn(fmaxf(x + bx, 0.0f), fmaxf(y + by, 0.0f));
    return *reinterpret_cast<uint32_t*>(&h);
}
__device__ __forceinline__ uint32_t lds_u32(const __half* p) {
    return *reinterpret_cast<const uint32_t*>(p);
}

// ---------------------------------------------------------------------------
// Kernel 1: transpose (S,Vin,C,D,H,W) fp32 -> (S*Vin,D,H,W,C) fp16, x(1/3)
// (verified: ~52-54us @ ~72% DRAM, at traffic floor)
// ---------------------------------------------------------------------------
__global__ void transpose_kernel(const float* __restrict__ enc) {
    int vox = blockIdx.x * blockDim.x + threadIdx.x;
    if (vox >= kNVox) return;
    int sv = vox / kDHW;
    int p  = vox - sv * kDHW;
    const float* src = enc + sv * (kC * kDHW) + p;
    const float third = 1.0f / 3.0f;
    unsigned h[8];
#pragma unroll
    for (int i = 0; i < 8; i++) {
        float a = src[(2 * i) * kDHW] * third;
        float b = src[(2 * i + 1) * kDHW] * third;
        __half2 hh = __floats2half2_rn(a, b);
        h[i] = *reinterpret_cast<unsigned*>(&hh);
    }
    uint4* dst = reinterpret_cast<uint4*>(g_encT + (size_t)vox * kC);
    dst[0] = make_uint4(h[0], h[1], h[2], h[3]);
    dst[1] = make_uint4(h[4], h[5], h[6], h[7]);
}

// ---------------------------------------------------------------------------
// Kernel 2: render. Block = 256 thr = 4 rays x 64 samples (R12 structure).
// MLP via mma.sync m16n8k16. Occupancy: 4 CTAs/SM via launch_bounds.
// ---------------------------------------------------------------------------
__global__ __launch_bounds__(256, 4) void render_kernel(
    const float* __restrict__ tposes,
    const float* __restrict__ iposes,
    const float* __restrict__ fp,
    const float* __restrict__ znp,
    const float* __restrict__ zfp,
    const float* __restrict__ W1, const float* __restrict__ b1,
    const float* __restrict__ W2, const float* __restrict__ b2,
    const float* __restrict__ W3, const float* __restrict__ b3)
{
    __shared__ __half sW1t[64][24];        // [n=j][k=c], stride 24 halves
    __shared__ __half sW2t[64][72];        // [n=j][k],   stride 72 halves
    __shared__ __half sW3t[24][72];        // [n=m][k=j], rows 17..23 zero
    __shared__ __align__(8) float sB1[64];
    __shared__ __align__(8) float sB2[64];
    __shared__ float sB3[17];
    __shared__ __align__(16) __half sFeat[8][32][16];   // [warp][sample][c]
    __shared__ float sOut[8][32][24];      // [warp][sample][m] (17 used, 24 padded)
    __shared__ float sWS[4][2];
    __shared__ float sRed[4][2][16];

    const int tid  = threadIdx.x;
    const int warp = tid >> 5;
    const int lane = tid & 31;

    // ---- stage weights (fp16, transposed) ----
    for (int i = tid; i < 24 * 36; i += 256)   // zero W3 tile (24*72 halves)
        reinterpret_cast<uint32_t*>(&sW3t[0][0])[i] = 0;
    __syncthreads();
    for (int i = tid; i < 1024; i += 256) {    // W1t[j][c] = W1[c][j]
        int j = i >> 4, c = i & 15;
        sW1t[j][c] = __float2half(W1[c * 64 + j]);
    }
    for (int i = tid; i < 4096; i += 256) {    // W2t[j][k] = W2[k][j]
        int j = i >> 6, k = i & 63;
        sW2t[j][k] = __float2half(W2[k * 64 + j]);
    }
    for (int i = tid; i < 1088; i += 256) {    // W3t[m][j] = W3[j][m]
        int m = i >> 6, j = i & 63;
        sW3t[m][j] = __float2half(W3[j * 17 + m]);
    }
    if (tid < 64) { sB1[tid] = b1[tid]; sB2[tid] = b2[tid]; }
    if (tid < 17) sB3[tid] = b3[tid];
    __syncthreads();

    const int rb = tid >> 6;          // ray within block (0..3)
    const int rt = tid & 63;          // sample index along ray
    const int wr = rt >> 5;           // warp within ray (0/1)

    const int ray = blockIdx.x * 4 + rb;
    const int sv  = ray / (kHlo * kWlo);
    const int pix = ray - sv * (kHlo * kWlo);
    const int py  = pix / kWlo;
    const int px  = pix - py * kWlo;
    const int s   = sv / kVt;

    const float focal = *fp;
    const float zn = *znp, zf = *zfp;

    const float* P = tposes + sv * 16;
    const float dcx = ((((float)px + 0.5f) / kWlo) * 2.0f - 1.0f) / focal;
    const float dcy = -(((((float)py + 0.5f) / kHlo) * 2.0f - 1.0f) / focal);
    const float dirx = P[0] * dcx + P[1] * dcy - P[2];
    const float diry = P[4] * dcx + P[5] * dcy - P[6];
    const float dirz = P[8] * dcx + P[9] * dcy - P[10];

    const float t = zn + (zf - zn) * ((float)rt / 63.0f);
    const float ptx = P[3] + t * dirx;
    const float pty = P[7] + t * diry;
    const float ptz = P[11] + t * dirz;

    const float minz = focal * zn;
    const float maxz = focal * zf;
    const float wdscale = 2.0f / (maxz - minz);

    // --- 3-view trilinear gather (channel-last fp16 volume), branch-free ---
    u64 fa[8];
#pragma unroll
    for (int q = 0; q < 8; q++) fa[q] = 0ull;

#pragma unroll
    for (int v = 0; v < kVin; v++) {
        const float* IP = iposes + (s * kVin + v) * 16;
        const float dx = ptx - IP[3];
        const float dy = pty - IP[7];
        const float dz = ptz - IP[11];
        const float lx = IP[0] * dx + IP[4] * dy + IP[8]  * dz;
        const float ly = IP[1] * dx + IP[5] * dy + IP[9]  * dz;
        const float lz = IP[2] * dx + IP[6] * dy + IP[10] * dz;
        const float z  = -lz;
        const float invz = focal / z;
        const float gx = lx * invz;
        const float gy = -(ly * invz);
        const float gz = -((z - minz) * wdscale - 1.0f);

        const float ixf = (gx + 1.0f) * (0.5f * kW) - 0.5f;
        const float iyf = (gy + 1.0f) * (0.5f * kH) - 0.5f;
        const float izf = (gz + 1.0f) * (0.5f * kD) - 0.5f;

        const float xf0 = floorf(ixf), yf0 = floorf(iyf), zf0 = floorf(izf);
        const int ix0 = (int)xf0, iy0 = (int)yf0, iz0 = (int)zf0;
        const int ix1 = ix0 + 1, iy1 = iy0 + 1, iz1 = iz0 + 1;
        const float fx = ixf - xf0, fy = iyf - yf0, fz = izf - zf0;

        const float wx0 = (ix0 >= 0 && ix0 < kW) ? (1.0f - fx) : 0.0f;
        const float wx1 = (ix1 >= 0 && ix1 < kW) ? fx : 0.0f;
        const float wy0 = (iy0 >= 0 && iy0 < kH) ? (1.0f - fy) : 0.0f;
        const float wy1 = (iy1 >= 0 && iy1 < kH) ? fy : 0.0f;
        const float wz0 = (iz0 >= 0 && iz0 < kD) ? (1.0f - fz) : 0.0f;
        const float wz1 = (iz1 >= 0 && iz1 < kD) ? fz : 0.0f;
        const int xi0 = min(max(ix0, 0), kW - 1);
        const int xi1 = min(max(ix1, 0), kW - 1);
        const int yi0 = min(max(iy0, 0), kH - 1);
        const int yi1 = min(max(iy1, 0), kH - 1);
        const int zi0 = min(max(iz0, 0), kD - 1);
        const int zi1 = min(max(iz1, 0), kD - 1);

        const int svin = s * kVin + v;
        const int rowb[4] = {
            ((svin * kD + zi0) * kH + yi0) * kW,
            ((svin * kD + zi0) * kH + yi1) * kW,
            ((svin * kD + zi1) * kH + yi0) * kW,
            ((svin * kD + zi1) * kH + yi1) * kW };
        const float wzy[4] = { wz0 * wy0, wz0 * wy1, wz1 * wy0, wz1 * wy1 };

#pragma unroll
        for (int e = 0; e < 4; e++) {
            const uint4* p0 = reinterpret_cast<const uint4*>(
                g_encT + (size_t)(rowb[e] + xi0) * kC);
            const uint4* p1 = reinterpret_cast<const uint4*>(
                g_encT + (size_t)(rowb[e] + xi1) * kC);
            uint4 a0 = p0[0], a1 = p0[1];
            uint4 b0 = p1[0], b1 = p1[1];
            const float w0s = wzy[e] * wx0;
            const float w1s = wzy[e] * wx1;
            const u64 w0 = pack2(w0s, w0s);
            const u64 w1 = pack2(w1s, w1s);
            fa[0] = ffma2(w0, h2f2p(a0.x), fa[0]);
            fa[1] = ffma2(w0, h2f2p(a0.y), fa[1]);
            fa[2] = ffma2(w0, h2f2p(a0.z), fa[2]);
            fa[3] = ffma2(w0, h2f2p(a0.w), fa[3]);
            fa[4] = ffma2(w0, h2f2p(a1.x), fa[4]);
            fa[5] = ffma2(w0, h2f2p(a1.y), fa[5]);
            fa[6] = ffma2(w0, h2f2p(a1.z), fa[6]);
            fa[7] = ffma2(w0, h2f2p(a1.w), fa[7]);
            fa[0] = ffma2(w1, h2f2p(b0.x), fa[0]);
            fa[1] = ffma2(w1, h2f2p(b0.y), fa[1]);
            fa[2] = ffma2(w1, h2f2p(b0.z), fa[2]);
            fa[3] = ffma2(w1, h2f2p(b0.w), fa[3]);
            fa[4] = ffma2(w1, h2f2p(b1.x), fa[4]);
            fa[5] = ffma2(w1, h2f2p(b1.y), fa[5]);
            fa[6] = ffma2(w1, h2f2p(b1.z), fa[6]);
            fa[7] = ffma2(w1, h2f2p(b1.w), fa[7]);
        }
    }

    // --- stage feats (fp16) into per-warp shared tile [sample][c] ---
    {
        uint32_t h2w[8];
#pragma unroll
        for (int q = 0; q < 8; q++) {
            float2 f = unpack2(fa[q]);
            __half2 hh = __floats2half2_rn(f.x, f.y);
            h2w[q] = *reinterpret_cast<uint32_t*>(&hh);
        }
        uint4* dst = reinterpret_cast<uint4*>(&sFeat[warp][lane][0]);
        dst[0] = make_uint4(h2w[0], h2w[1], h2w[2], h2w[3]);
        dst[1] = make_uint4(h2w[4], h2w[5], h2w[6], h2w[7]);
    }
    __syncwarp();

    const int r = lane >> 2;          // fragment row group 0..7
    const int q = lane & 3;           // fragment col group 0..3
    const int k0 = 2 * q;             // low k index (halves)

    // ---- A1 fragments (m16k16 x 2 m-tiles) from sFeat ----
    uint32_t A1[2][4];
#pragma unroll
    for (int mt = 0; mt < 2; mt++) {
        const int rowb = mt * 16;
        A1[mt][0] = lds_u32(&sFeat[warp][rowb + r][k0]);
        A1[mt][1] = lds_u32(&sFeat[warp][rowb + r + 8][k0]);
        A1[mt][2] = lds_u32(&sFeat[warp][rowb + r][k0 + 8]);
        A1[mt][3] = lds_u32(&sFeat[warp][rowb + r + 8][k0 + 8]);
    }

    // ---- Layer 1: 16 -> 64, produce A2 fragments ----
    uint32_t A2[2][4][4];   // [mt][ktile][a0..a3]
#pragma unroll
    for (int jp = 0; jp < 4; jp++) {
        float C[2][2][4];
#pragma unroll
        for (int mt = 0; mt < 2; mt++)
#pragma unroll
            for (int jin = 0; jin < 2; jin++)
#pragma unroll
                for (int e = 0; e < 4; e++) C[mt][jin][e] = 0.0f;
#pragma unroll
        for (int jin = 0; jin < 2; jin++) {
            const int j = 2 * jp + jin;
            const uint32_t b0 = lds_u32(&sW1t[8 * j + r][k0]);
            const uint32_t b1 = lds_u32(&sW1t[8 * j + r][k0 + 8]);
#pragma unroll
            for (int mt = 0; mt < 2; mt++)
                mma16816(C[mt][jin][0], C[mt][jin][1], C[mt][jin][2], C[mt][jin][3],
                         A1[mt][0], A1[mt][1], A1[mt][2], A1[mt][3], b0, b1);
        }
        const float2 bA = *reinterpret_cast<const float2*>(&sB1[16 * jp + k0]);
        const float2 bB = *reinterpret_cast<const float2*>(&sB1[16 * jp + 8 + k0]);
#pragma unroll
        for (int mt = 0; mt < 2; mt++) {
            A2[mt][jp][0] = packrelu(C[mt][0][0], C[mt][0][1], bA.x, bA.y);
            A2[mt][jp][1] = packrelu(C[mt][0][2], C[mt][0][3], bA.x, bA.y);
            A2[mt][jp][2] = packrelu(C[mt][1][0], C[mt][1][1], bB.x, bB.y);
            A2[mt][jp][3] = packrelu(C[mt][1][2], C[mt][1][3], bB.x, bB.y);
        }
    }

    // ---- Layer 2: 64 -> 64, produce A3 fragments ----
    uint32_t A3[2][4][4];
#pragma unroll
    for (int jp = 0; jp < 4; jp++) {
        float C[2][2][4];
#pragma unroll
        for (int mt = 0; mt < 2; mt++)
#pragma unroll
            for (int jin = 0; jin < 2; jin++)
#pragma unroll
                for (int e = 0; e < 4; e++) C[mt][jin][e] = 0.0f;
#pragma unroll
        for (int jin = 0; jin < 2; jin++) {
            const int j = 2 * jp + jin;
#pragma unroll
            for (int kk = 0; kk < 4; kk++) {
                const uint32_t b0 = lds_u32(&sW2t[8 * j + r][16 * kk + k0]);
                const uint32_t b1 = lds_u32(&sW2t[8 * j + r][16 * kk + k0 + 8]);
#pragma unroll
                for (int mt = 0; mt < 2; mt++)
                    mma16816(C[mt][jin][0], C[mt][jin][1], C[mt][jin][2], C[mt][jin][3],
                             A2[mt][kk][0], A2[mt][kk][1], A2[mt][kk][2], A2[mt][kk][3],
                             b0, b1);
            }
        }
        const float2 bA = *reinterpret_cast<const float2*>(&sB2[16 * jp + k0]);
        const float2 bB = *reinterpret_cast<const float2*>(&sB2[16 * jp + 8 + k0]);
#pragma unroll
        for (int mt = 0; mt < 2; mt++) {
            A3[mt][jp][0] = packrelu(C[mt][0][0], C[mt][0][1], bA.x, bA.y);
            A3[mt][jp][1] = packrelu(C[mt][0][2], C[mt][0][3], bA.x, bA.y);
            A3[mt][jp][2] = packrelu(C[mt][1][0], C[mt][1][1], bB.x, bB.y);
            A3[mt][jp][3] = packrelu(C[mt][1][2], C[mt][1][3], bB.x, bB.y);
        }
    }

    // ---- Layer 3: 64 -> 17 (3 n-tiles, padded to 24) ----
#pragma unroll
    for (int j = 0; j < 3; j++) {
        float C[2][4];
#pragma unroll
        for (int mt = 0; mt < 2; mt++)
#pragma unroll
            for (int e = 0; e < 4; e++) C[mt][e] = 0.0f;
#pragma unroll
        for (int kk = 0; kk < 4; kk++) {
            const uint32_t b0 = lds_u32(&sW3t[8 * j + r][16 * kk + k0]);
            const uint32_t b1 = lds_u32(&sW3t[8 * j + r][16 * kk + k0 + 8]);
#pragma unroll
            for (int mt = 0; mt < 2; mt++)
                mma16816(C[mt][0], C[mt][1], C[mt][2], C[mt][3],
                         A3[mt][kk][0], A3[mt][kk][1], A3[mt][kk][2], A3[mt][kk][3],
                         b0, b1);
        }
        const int col = 8 * j + k0;
#pragma unroll
        for (int mt = 0; mt < 2; mt++) {
            const int row0 = mt * 16 + r;
            sOut[warp][row0][col]     = C[mt][0];
            sOut[warp][row0][col + 1] = C[mt][1];
            sOut[warp][row0 + 8][col]     = C[mt][2];
            sOut[warp][row0 + 8][col + 1] = C[mt][3];
        }
    }
    __syncwarp();

    // ---- per-sample outputs ----
    float o[17];
#pragma unroll
    for (int m = 0; m < 17; m++)
        o[m] = sOut[warp][lane][m] + sB3[m];

    float feats[16];
    {
        const uint32_t* fsrc = reinterpret_cast<const uint32_t*>(&sFeat[warp][lane][0]);
#pragma unroll
        for (int qq = 0; qq < 8; qq++) {
            uint32_t uu = fsrc[qq];
            __half2 hh = *reinterpret_cast<__half2*>(&uu);
            float2 ff = __half22float2(hh);
            feats[2 * qq] = ff.x; feats[2 * qq + 1] = ff.y;
        }
    }

    const float density = fmaxf(o[0], 0.0f);
    const float delta = (rt == 63) ? 1e10f : (zf - zn) * (1.0f / 63.0f);
    const float sd = density * delta;

    // Inclusive scan of sd across the 64 threads of this ray
    const int slane = rt & 31;
    float vscan = sd;
#pragma unroll
    for (int off = 1; off < 32; off <<= 1) {
        float n = __shfl_up_sync(0xffffffffu, vscan, off);
        if (slane >= off) vscan += n;
    }
    if (slane == 31) sWS[rb][wr] = vscan;
    __syncthreads();
    const float cum = vscan + ((wr == 1) ? sWS[rb][0] : 0.0f);
    const float T = __expf(-cum);
    const float alpha = 1.0f - __expf(-sd);
    const float wgt = alpha * T;

#pragma unroll
    for (int c = 0; c < 16; c++) {
        float val = wgt * (feats[c] + o[c + 1]);
#pragma unroll
        for (int off = 16; off > 0; off >>= 1)
            val += __shfl_down_sync(0xffffffffu, val, off);
        if (slane == 0) sRed[rb][wr][c] = val;
    }
    __syncthreads();
    if (rt < 16) {
        g_rlo[((sv * kC + rt) * kHlo + py) * kWlo + px] =
            sRed[rb][0][rt] + sRed[rb][1][rt];
    }
}

// ---------------------------------------------------------------------------
// Kernel 3: 2x bilinear upsample, align_corners=True (48 -> 96)
// ---------------------------------------------------------------------------
__global__ void upsample_kernel(float* __restrict__ out) {
    const int n = blockIdx.x * blockDim.x + threadIdx.x;
    constexpr int kTot = kS * kVt * kC * kH * kW;
    if (n >= kTot) return;
    const int x = n % kW;
    const int y = (n / kW) % kH;
    const int svc = n / (kH * kW);

    const float pxf = (float)x * (47.0f / 95.0f);
    const float pyf = (float)y * (47.0f / 95.0f);
    const int lx = (int)pxf; const int hx = min(lx + 1, 47);
    const int ly = (int)pyf; const int hy = min(ly + 1, 47);
    const float fx = pxf - (float)lx;
    const float fy = pyf - (float)ly;

    const float* r = g_rlo + svc * (kHlo * kWlo);
    const float v00 = r[ly * kWlo + lx];
    const float v01 = r[ly * kWlo + hx];
    const float v10 = r[hy * kWlo + lx];
    const float v11 = r[hy * kWlo + hx];
    out[n] = (v00 * (1.0f - fx) + v01 * fx) * (1.0f - fy)
           + (v10 * (1.0f - fx) + v11 * fx) * fy;
}

// ---------------------------------------------------------------------------
extern "C" void kernel_launch(void* const* d_in, const int* in_sizes, int n_in,
                              void* d_out, int out_size) {
    const float* enc = (const float*)d_in[0];
    const float* ipo = (const float*)d_in[1];
    const float* tpo = (const float*)d_in[2];
    const float* fp  = (const float*)d_in[3];
    const float* znp = (const float*)d_in[4];
    const float* zfp = (const float*)d_in[5];
    const float* W1 = (const float*)d_in[7];
    const float* b1 = (const float*)d_in[8];
    const float* W2 = (const float*)d_in[9];
    const float* b2 = (const float*)d_in[10];
    const float* W3 = (const float*)d_in[11];
    const float* b3 = (const float*)d_in[12];
    float* out = (float*)d_out;

    transpose_kernel<<<(kNVox + 255) / 256, 256>>>(enc);
    render_kernel<<<kRays / 4, 256>>>(tpo, ipo, fp, znp, zfp,
                                      W1, b1, W2, b2, W3, b3);
    constexpr int kTot = kS * kVt * kC * kH * kW;
    upsample_kernel<<<(kTot + 255) / 256, 256>>>(out);
}

// round 14
// speedup vs baseline: 1.4065x; 1.4065x over previous
#include <cuda_runtime.h>
#include <cuda_fp16.h>
#include <cstdint>

// Static problem shapes (from setup_inputs)
constexpr int kS   = 2;
constexpr int kVin = 3;
constexpr int kVt  = 4;
constexpr int kC   = 16;
constexpr int kD   = 64;
constexpr int kH   = 96;
constexpr int kW   = 96;
constexpr int kHlo = 48;
constexpr int kWlo = 48;

constexpr int kDHW  = kD * kH * kW;           // 589824
constexpr int kNVox = kS * kVin * kDHW;       // 3,538,944
constexpr int kRays = kS * kVt * kHlo * kWlo; // 18432

// Scratch: channel-last fp16 volume (113 MB), pre-scaled by 1/3
__device__ __half g_encT[(size_t)kNVox * kC];
__device__ float  g_rlo[kS * kVt * kC * kHlo * kWlo];

// ---------------- packed f32x2 helpers (sm_103a) ----------------
using u64 = unsigned long long;
__device__ __forceinline__ u64 pack2(float lo, float hi) {
    u64 r; asm("mov.b64 %0,{%1,%2};" : "=l"(r) : "f"(lo), "f"(hi)); return r;
}
__device__ __forceinline__ float2 unpack2(u64 v) {
    float2 f; asm("mov.b64 {%0,%1},%2;" : "=f"(f.x), "=f"(f.y) : "l"(v)); return f;
}
__device__ __forceinline__ u64 ffma2(u64 a, u64 b, u64 c) {
    u64 d; asm("fma.rn.f32x2 %0,%1,%2,%3;" : "=l"(d) : "l"(a), "l"(b), "l"(c)); return d;
}
__device__ __forceinline__ u64 h2f2p(unsigned u) {
    __half2 h = *reinterpret_cast<__half2*>(&u);
    float2 f = __half22float2(h);
    return pack2(f.x, f.y);
}

// ---------------- mma.sync m16n8k16 helper (tensor pipe) ----------------
__device__ __forceinline__ void mma16816(float& c0, float& c1, float& c2, float& c3,
                                         uint32_t a0, uint32_t a1, uint32_t a2, uint32_t a3,
                                         uint32_t b0, uint32_t b1) {
    asm volatile(
        "mma.sync.aligned.m16n8k16.row.col.f32.f16.f16.f32 "
        "{%0,%1,%2,%3}, {%4,%5,%6,%7}, {%8,%9}, {%0,%1,%2,%3};"
        : "+f"(c0), "+f"(c1), "+f"(c2), "+f"(c3)
        : "r"(a0), "r"(a1), "r"(a2), "r"(a3), "r"(b0), "r"(b1));
}
__device__ __forceinline__ uint32_t packrelu(float x, float y, float bx, float by) {
    __half2 h = __floats2half2_rn(fmaxf(x + bx, 0.0f), fmaxf(y + by, 0.0f));
    return *reinterpret_cast<uint32_t*>(&h);
}
__device__ __forceinline__ uint32_t lds_u32(const __half* p) {
    return *reinterpret_cast<const uint32_t*>(p);
}

// ---------------------------------------------------------------------------
// Kernel 1: transpose (S,Vin,C,D,H,W) fp32 -> (S*Vin,D,H,W,C) fp16, x(1/3)
// (verified: ~52-54us @ ~72% DRAM, at traffic floor)
// ---------------------------------------------------------------------------
__global__ void transpose_kernel(const float* __restrict__ enc) {
    int vox = blockIdx.x * blockDim.x + threadIdx.x;
    if (vox >= kNVox) return;
    int sv = vox / kDHW;
    int p  = vox - sv * kDHW;
    const float* src = enc + sv * (kC * kDHW) + p;
    const float third = 1.0f / 3.0f;
    unsigned h[8];
#pragma unroll
    for (int i = 0; i < 8; i++) {
        float a = src[(2 * i) * kDHW] * third;
        float b = src[(2 * i + 1) * kDHW] * third;
        __half2 hh = __floats2half2_rn(a, b);
        h[i] = *reinterpret_cast<unsigned*>(&hh);
    }
    uint4* dst = reinterpret_cast<uint4*>(g_encT + (size_t)vox * kC);
    dst[0] = make_uint4(h[0], h[1], h[2], h[3]);
    dst[1] = make_uint4(h[4], h[5], h[6], h[7]);
}

// ---------------------------------------------------------------------------
// Kernel 2: render. Block = 256 thr = 4 rays x 64 samples (R12 structure).
// MLP via mma.sync m16n8k16. 3 CTAs/SM. Gather: address precompute phase
// decoupled from the load/accumulate phase (better cross-view LDG overlap).
// ---------------------------------------------------------------------------
__global__ __launch_bounds__(256, 3) void render_kernel(
    const float* __restrict__ tposes,
    const float* __restrict__ iposes,
    const float* __restrict__ fp,
    const float* __restrict__ znp,
    const float* __restrict__ zfp,
    const float* __restrict__ W1, const float* __restrict__ b1,
    const float* __restrict__ W2, const float* __restrict__ b2,
    const float* __restrict__ W3, const float* __restrict__ b3)
{
    __shared__ __half sW1t[64][24];        // [n=j][k=c], stride 24 halves
    __shared__ __half sW2t[64][72];        // [n=j][k],   stride 72 halves
    __shared__ __half sW3t[24][72];        // [n=m][k=j], rows 17..23 zero
    __shared__ __align__(8) float sB1[64];
    __shared__ __align__(8) float sB2[64];
    __shared__ float sB3[17];
    __shared__ __align__(16) __half sFeat[8][32][16];   // [warp][sample][c]
    __shared__ float sOut[8][32][24];      // [warp][sample][m] (17 used, 24 padded)
    __shared__ float sWS[4][2];
    __shared__ float sRed[4][2][16];

    const int tid  = threadIdx.x;
    const int warp = tid >> 5;
    const int lane = tid & 31;

    // ---- stage weights (fp16, transposed) ----
    for (int i = tid; i < 24 * 36; i += 256)   // zero W3 tile (24*72 halves)
        reinterpret_cast<uint32_t*>(&sW3t[0][0])[i] = 0;
    __syncthreads();
    for (int i = tid; i < 1024; i += 256) {    // W1t[j][c] = W1[c][j]
        int j = i >> 4, c = i & 15;
        sW1t[j][c] = __float2half(W1[c * 64 + j]);
    }
    for (int i = tid; i < 4096; i += 256) {    // W2t[j][k] = W2[k][j]
        int j = i >> 6, k = i & 63;
        sW2t[j][k] = __float2half(W2[k * 64 + j]);
    }
    for (int i = tid; i < 1088; i += 256) {    // W3t[m][j] = W3[j][m]
        int m = i >> 6, j = i & 63;
        sW3t[m][j] = __float2half(W3[j * 17 + m]);
    }
    if (tid < 64) { sB1[tid] = b1[tid]; sB2[tid] = b2[tid]; }
    if (tid < 17) sB3[tid] = b3[tid];
    __syncthreads();

    const int rb = tid >> 6;          // ray within block (0..3)
    const int rt = tid & 63;          // sample index along ray
    const int wr = rt >> 5;           // warp within ray (0/1)

    const int ray = blockIdx.x * 4 + rb;
    const int sv  = ray / (kHlo * kWlo);
    const int pix = ray - sv * (kHlo * kWlo);
    const int py  = pix / kWlo;
    const int px  = pix - py * kWlo;
    const int s   = sv / kVt;

    const float focal = *fp;
    const float zn = *znp, zf = *zfp;

    const float* P = tposes + sv * 16;
    const float dcx = ((((float)px + 0.5f) / kWlo) * 2.0f - 1.0f) / focal;
    const float dcy = -(((((float)py + 0.5f) / kHlo) * 2.0f - 1.0f) / focal);
    const float dirx = P[0] * dcx + P[1] * dcy - P[2];
    const float diry = P[4] * dcx + P[5] * dcy - P[6];
    const float dirz = P[8] * dcx + P[9] * dcy - P[10];

    const float t = zn + (zf - zn) * ((float)rt / 63.0f);
    const float ptx = P[3] + t * dirx;
    const float pty = P[7] + t * diry;
    const float ptz = P[11] + t * dirz;

    const float minz = focal * zn;
    const float maxz = focal * zf;
    const float wdscale = 2.0f / (maxz - minz);

    // --- Phase A: precompute all 3 views' gather addresses + weights ---
    const __half* base0[kVin];   // &g_encT[(rowb+xi0)*kC] per (v,e)... flattened
    // flatten: per view 4 row-pair bases for xi0 and xi1, plus weights
    int  offs0[kVin][4];
    int  offs1[kVin][4];
    float wgt0[kVin][4];
    float wgt1[kVin][4];
    (void)base0;

#pragma unroll
    for (int v = 0; v < kVin; v++) {
        const float* IP = iposes + (s * kVin + v) * 16;
        const float dx = ptx - IP[3];
        const float dy = pty - IP[7];
        const float dz = ptz - IP[11];
        const float lx = IP[0] * dx + IP[4] * dy + IP[8]  * dz;
        const float ly = IP[1] * dx + IP[5] * dy + IP[9]  * dz;
        const float lz = IP[2] * dx + IP[6] * dy + IP[10] * dz;
        const float z  = -lz;
        const float invz = focal / z;
        const float gx = lx * invz;
        const float gy = -(ly * invz);
        const float gz = -((z - minz) * wdscale - 1.0f);

        const float ixf = (gx + 1.0f) * (0.5f * kW) - 0.5f;
        const float iyf = (gy + 1.0f) * (0.5f * kH) - 0.5f;
        const float izf = (gz + 1.0f) * (0.5f * kD) - 0.5f;

        const float xf0 = floorf(ixf), yf0 = floorf(iyf), zf0 = floorf(izf);
        const int ix0 = (int)xf0, iy0 = (int)yf0, iz0 = (int)zf0;
        const int ix1 = ix0 + 1, iy1 = iy0 + 1, iz1 = iz0 + 1;
        const float fx = ixf - xf0, fy = iyf - yf0, fz = izf - zf0;

        const float wx0 = (ix0 >= 0 && ix0 < kW) ? (1.0f - fx) : 0.0f;
        const float wx1 = (ix1 >= 0 && ix1 < kW) ? fx : 0.0f;
        const float wy0 = (iy0 >= 0 && iy0 < kH) ? (1.0f - fy) : 0.0f;
        const float wy1 = (iy1 >= 0 && iy1 < kH) ? fy : 0.0f;
        const float wz0 = (iz0 >= 0 && iz0 < kD) ? (1.0f - fz) : 0.0f;
        const float wz1 = (iz1 >= 0 && iz1 < kD) ? fz : 0.0f;
        const int xi0 = min(max(ix0, 0), kW - 1);
        const int xi1 = min(max(ix1, 0), kW - 1);
        const int yi0 = min(max(iy0, 0), kH - 1);
        const int yi1 = min(max(iy1, 0), kH - 1);
        const int zi0 = min(max(iz0, 0), kD - 1);
        const int zi1 = min(max(iz1, 0), kD - 1);

        const int svin = s * kVin + v;
        const int r00 = ((svin * kD + zi0) * kH + yi0) * kW;
        const int r01 = ((svin * kD + zi0) * kH + yi1) * kW;
        const int r10 = ((svin * kD + zi1) * kH + yi0) * kW;
        const int r11 = ((svin * kD + zi1) * kH + yi1) * kW;
        const int rr[4] = { r00, r01, r10, r11 };
        const float ww[4] = { wz0 * wy0, wz0 * wy1, wz1 * wy0, wz1 * wy1 };
#pragma unroll
        for (int e = 0; e < 4; e++) {
            offs0[v][e] = rr[e] + xi0;
            offs1[v][e] = rr[e] + xi1;
            wgt0[v][e]  = ww[e] * wx0;
            wgt1[v][e]  = ww[e] * wx1;
        }
    }

    // --- Phase B: loads + accumulate (addresses all ready -> deep LDG overlap) ---
    u64 fa[8];
#pragma unroll
    for (int q = 0; q < 8; q++) fa[q] = 0ull;

#pragma unroll
    for (int v = 0; v < kVin; v++) {
#pragma unroll
        for (int e = 0; e < 4; e++) {
            const uint4* p0 = reinterpret_cast<const uint4*>(
                g_encT + (size_t)offs0[v][e] * kC);
            const uint4* p1 = reinterpret_cast<const uint4*>(
                g_encT + (size_t)offs1[v][e] * kC);
            uint4 a0 = p0[0], a1 = p0[1];
            uint4 b0 = p1[0], b1 = p1[1];
            const u64 w0 = pack2(wgt0[v][e], wgt0[v][e]);
            const u64 w1 = pack2(wgt1[v][e], wgt1[v][e]);
            fa[0] = ffma2(w0, h2f2p(a0.x), fa[0]);
            fa[1] = ffma2(w0, h2f2p(a0.y), fa[1]);
            fa[2] = ffma2(w0, h2f2p(a0.z), fa[2]);
            fa[3] = ffma2(w0, h2f2p(a0.w), fa[3]);
            fa[4] = ffma2(w0, h2f2p(a1.x), fa[4]);
            fa[5] = ffma2(w0, h2f2p(a1.y), fa[5]);
            fa[6] = ffma2(w0, h2f2p(a1.z), fa[6]);
            fa[7] = ffma2(w0, h2f2p(a1.w), fa[7]);
            fa[0] = ffma2(w1, h2f2p(b0.x), fa[0]);
            fa[1] = ffma2(w1, h2f2p(b0.y), fa[1]);
            fa[2] = ffma2(w1, h2f2p(b0.z), fa[2]);
            fa[3] = ffma2(w1, h2f2p(b0.w), fa[3]);
            fa[4] = ffma2(w1, h2f2p(b1.x), fa[4]);
            fa[5] = ffma2(w1, h2f2p(b1.y), fa[5]);
            fa[6] = ffma2(w1, h2f2p(b1.z), fa[6]);
            fa[7] = ffma2(w1, h2f2p(b1.w), fa[7]);
        }
    }

    // --- stage feats (fp16) into per-warp shared tile [sample][c] ---
    {
        uint32_t h2w[8];
#pragma unroll
        for (int q = 0; q < 8; q++) {
            float2 f = unpack2(fa[q]);
            __half2 hh = __floats2half2_rn(f.x, f.y);
            h2w[q] = *reinterpret_cast<uint32_t*>(&hh);
        }
        uint4* dst = reinterpret_cast<uint4*>(&sFeat[warp][lane][0]);
        dst[0] = make_uint4(h2w[0], h2w[1], h2w[2], h2w[3]);
        dst[1] = make_uint4(h2w[4], h2w[5], h2w[6], h2w[7]);
    }
    __syncwarp();

    const int r = lane >> 2;          // fragment row group 0..7
    const int q = lane & 3;           // fragment col group 0..3
    const int k0 = 2 * q;             // low k index (halves)

    // ---- A1 fragments (m16k16 x 2 m-tiles) from sFeat ----
    uint32_t A1[2][4];
#pragma unroll
    for (int mt = 0; mt < 2; mt++) {
        const int rowb = mt * 16;
        A1[mt][0] = lds_u32(&sFeat[warp][rowb + r][k0]);
        A1[mt][1] = lds_u32(&sFeat[warp][rowb + r + 8][k0]);
        A1[mt][2] = lds_u32(&sFeat[warp][rowb + r][k0 + 8]);
        A1[mt][3] = lds_u32(&sFeat[warp][rowb + r + 8][k0 + 8]);
    }

    // ---- Layer 1: 16 -> 64, produce A2 fragments ----
    uint32_t A2[2][4][4];   // [mt][ktile][a0..a3]
#pragma unroll
    for (int jp = 0; jp < 4; jp++) {
        float C[2][2][4];
#pragma unroll
        for (int mt = 0; mt < 2; mt++)
#pragma unroll
            for (int jin = 0; jin < 2; jin++)
#pragma unroll
                for (int e = 0; e < 4; e++) C[mt][jin][e] = 0.0f;
#pragma unroll
        for (int jin = 0; jin < 2; jin++) {
            const int j = 2 * jp + jin;
            const uint32_t b0 = lds_u32(&sW1t[8 * j + r][k0]);
            const uint32_t b1 = lds_u32(&sW1t[8 * j + r][k0 + 8]);
#pragma unroll
            for (int mt = 0; mt < 2; mt++)
                mma16816(C[mt][jin][0], C[mt][jin][1], C[mt][jin][2], C[mt][jin][3],
                         A1[mt][0], A1[mt][1], A1[mt][2], A1[mt][3], b0, b1);
        }
        const float2 bA = *reinterpret_cast<const float2*>(&sB1[16 * jp + k0]);
        const float2 bB = *reinterpret_cast<const float2*>(&sB1[16 * jp + 8 + k0]);
#pragma unroll
        for (int mt = 0; mt < 2; mt++) {
            A2[mt][jp][0] = packrelu(C[mt][0][0], C[mt][0][1], bA.x, bA.y);
            A2[mt][jp][1] = packrelu(C[mt][0][2], C[mt][0][3], bA.x, bA.y);
            A2[mt][jp][2] = packrelu(C[mt][1][0], C[mt][1][1], bB.x, bB.y);
            A2[mt][jp][3] = packrelu(C[mt][1][2], C[mt][1][3], bB.x, bB.y);
        }
    }

    // ---- Layer 2: 64 -> 64, produce A3 fragments ----
    uint32_t A3[2][4][4];
#pragma unroll
    for (int jp = 0; jp < 4; jp++) {
        float C[2][2][4];
#pragma unroll
        for (int mt = 0; mt < 2; mt++)
#pragma unroll
            for (int jin = 0; jin < 2; jin++)
#pragma unroll
                for (int e = 0; e < 4; e++) C[mt][jin][e] = 0.0f;
#pragma unroll
        for (int jin = 0; jin < 2; jin++) {
            const int j = 2 * jp + jin;
#pragma unroll
            for (int kk = 0; kk < 4; kk++) {
                const uint32_t b0 = lds_u32(&sW2t[8 * j + r][16 * kk + k0]);
                const uint32_t b1 = lds_u32(&sW2t[8 * j + r][16 * kk + k0 + 8]);
#pragma unroll
                for (int mt = 0; mt < 2; mt++)
                    mma16816(C[mt][jin][0], C[mt][jin][1], C[mt][jin][2], C[mt][jin][3],
                             A2[mt][kk][0], A2[mt][kk][1], A2[mt][kk][2], A2[mt][kk][3],
                             b0, b1);
            }
        }
        const float2 bA = *reinterpret_cast<const float2*>(&sB2[16 * jp + k0]);
        const float2 bB = *reinterpret_cast<const float2*>(&sB2[16 * jp + 8 + k0]);
#pragma unroll
        for (int mt = 0; mt < 2; mt++) {
            A3[mt][jp][0] = packrelu(C[mt][0][0], C[mt][0][1], bA.x, bA.y);
            A3[mt][jp][1] = packrelu(C[mt][0][2], C[mt][0][3], bA.x, bA.y);
            A3[mt][jp][2] = packrelu(C[mt][1][0], C[mt][1][1], bB.x, bB.y);
            A3[mt][jp][3] = packrelu(C[mt][1][2], C[mt][1][3], bB.x, bB.y);
        }
    }

    // ---- Layer 3: 64 -> 17 (3 n-tiles, padded to 24) ----
#pragma unroll
    for (int j = 0; j < 3; j++) {
        float C[2][4];
#pragma unroll
        for (int mt = 0; mt < 2; mt++)
#pragma unroll
            for (int e = 0; e < 4; e++) C[mt][e] = 0.0f;
#pragma unroll
        for (int kk = 0; kk < 4; kk++) {
            const uint32_t b0 = lds_u32(&sW3t[8 * j + r][16 * kk + k0]);
            const uint32_t b1 = lds_u32(&sW3t[8 * j + r][16 * kk + k0 + 8]);
#pragma unroll
            for (int mt = 0; mt < 2; mt++)
                mma16816(C[mt][0], C[mt][1], C[mt][2], C[mt][3],
                         A3[mt][kk][0], A3[mt][kk][1], A3[mt][kk][2], A3[mt][kk][3],
                         b0, b1);
        }
        const int col = 8 * j + k0;
#pragma unroll
        for (int mt = 0; mt < 2; mt++) {
            const int row0 = mt * 16 + r;
            sOut[warp][row0][col]     = C[mt][0];
            sOut[warp][row0][col + 1] = C[mt][1];
            sOut[warp][row0 + 8][col]     = C[mt][2];
            sOut[warp][row0 + 8][col + 1] = C[mt][3];
        }
    }
    __syncwarp();

    // ---- per-sample outputs ----
    float o[17];
#pragma unroll
    for (int m = 0; m < 17; m++)
        o[m] = sOut[warp][lane][m] + sB3[m];

    float feats[16];
    {
        const uint32_t* fsrc = reinterpret_cast<const uint32_t*>(&sFeat[warp][lane][0]);
#pragma unroll
        for (int qq = 0; qq < 8; qq++) {
            uint32_t uu = fsrc[qq];
            __half2 hh = *reinterpret_cast<__half2*>(&uu);
            float2 ff = __half22float2(hh);
            feats[2 * qq] = ff.x; feats[2 * qq + 1] = ff.y;
        }
    }

    const float density = fmaxf(o[0], 0.0f);
    const float delta = (rt == 63) ? 1e10f : (zf - zn) * (1.0f / 63.0f);
    const float sd = density * delta;

    // Inclusive scan of sd across the 64 threads of this ray
    const int slane = rt & 31;
    float vscan = sd;
#pragma unroll
    for (int off = 1; off < 32; off <<= 1) {
        float n = __shfl_up_sync(0xffffffffu, vscan, off);
        if (slane >= off) vscan += n;
    }
    if (slane == 31) sWS[rb][wr] = vscan;
    __syncthreads();
    const float cum = vscan + ((wr == 1) ? sWS[rb][0] : 0.0f);
    const float T = __expf(-cum);
    const float alpha = 1.0f - __expf(-sd);
    const float wgt = alpha * T;

#pragma unroll
    for (int c = 0; c < 16; c++) {
        float val = wgt * (feats[c] + o[c + 1]);
#pragma unroll
        for (int off = 16; off > 0; off >>= 1)
            val += __shfl_down_sync(0xffffffffu, val, off);
        if (slane == 0) sRed[rb][wr][c] = val;
    }
    __syncthreads();
    if (rt < 16) {
        g_rlo[((sv * kC + rt) * kHlo + py) * kWlo + px] =
            sRed[rb][0][rt] + sRed[rb][1][rt];
    }
}

// ---------------------------------------------------------------------------
// Kernel 3: 2x bilinear upsample, align_corners=True (48 -> 96), float4 out
// ---------------------------------------------------------------------------
__global__ void upsample_kernel(float* __restrict__ out) {
    const int n4 = blockIdx.x * blockDim.x + threadIdx.x;
    constexpr int kTot4 = kS * kVt * kC * kH * kW / 4;
    if (n4 >= kTot4) return;
    const int xq  = n4 % (kW / 4);        // group of 4 x
    const int y   = (n4 / (kW / 4)) % kH;
    const int svc = n4 / (kH * kW / 4);

    const float pyf = (float)y * (47.0f / 95.0f);
    const int ly = (int)pyf; const int hy = min(ly + 1, 47);
    const float fy = pyf - (float)ly;

    const float* rlo = g_rlo + svc * (kHlo * kWlo);
    const float* r0 = rlo + ly * kWlo;
    const float* r1 = rlo + hy * kWlo;

    float res[4];
#pragma unroll
    for (int i = 0; i < 4; i++) {
        const int x = xq * 4 + i;
        const float pxf = (float)x * (47.0f / 95.0f);
        const int lx = (int)pxf; const int hx = min(lx + 1, 47);
        const float fx = pxf - (float)lx;
        const float v0 = r0[lx] * (1.0f - fx) + r0[hx] * fx;
        const float v1 = r1[lx] * (1.0f - fx) + r1[hx] * fx;
        res[i] = v0 * (1.0f - fy) + v1 * fy;
    }
    reinterpret_cast<float4*>(out)[n4] =
        make_float4(res[0], res[1], res[2], res[3]);
}

// ---------------------------------------------------------------------------
extern "C" void kernel_launch(void* const* d_in, const int* in_sizes, int n_in,
                              void* d_out, int out_size) {
    const float* enc = (const float*)d_in[0];
    const float* ipo = (const float*)d_in[1];
    const float* tpo = (const float*)d_in[2];
    const float* fp  = (const float*)d_in[3];
    const float* znp = (const float*)d_in[4];
    const float* zfp = (const float*)d_in[5];
    const float* W1 = (const float*)d_in[7];
    const float* b1 = (const float*)d_in[8];
    const float* W2 = (const float*)d_in[9];
    const float* b2 = (const float*)d_in[10];
    const float* W3 = (const float*)d_in[11];
    const float* b3 = (const float*)d_in[12];
    float* out = (float*)d_out;

    transpose_kernel<<<(kNVox + 255) / 256, 256>>>(enc);
    render_kernel<<<kRays / 4, 256>>>(tpo, ipo, fp, znp, zfp,
                                      W1, b1, W2, b2, W3, b3);
    constexpr int kTot4 = kS * kVt * kC * kH * kW / 4;
    upsample_kernel<<<(kTot4 + 255) / 256, 256>>>(out);
}

// round 15
// speedup vs baseline: 1.6595x; 1.1799x over previous
#include <cuda_runtime.h>
#include <cuda_fp16.h>
#include <cstdint>

// Static problem shapes (from setup_inputs)
constexpr int kS   = 2;
constexpr int kVin = 3;
constexpr int kVt  = 4;
constexpr int kC   = 16;
constexpr int kD   = 64;
constexpr int kH   = 96;
constexpr int kW   = 96;
constexpr int kHlo = 48;
constexpr int kWlo = 48;

constexpr int kDHW  = kD * kH * kW;           // 589824
constexpr int kNVox = kS * kVin * kDHW;       // 3,538,944
constexpr int kRays = kS * kVt * kHlo * kWlo; // 18432
constexpr int kTiles = kRays / 4;             // 4608 ray-groups
constexpr int kPersistCTAs = 444;             // 3 per SM x 148 SMs

// Scratch: channel-last fp16 volume (113 MB), pre-scaled by 1/3
__device__ __half g_encT[(size_t)kNVox * kC];
__device__ float  g_rlo[kS * kVt * kC * kHlo * kWlo];

// ---------------- packed f32x2 helpers (sm_103a) ----------------
using u64 = unsigned long long;
__device__ __forceinline__ u64 pack2(float lo, float hi) {
    u64 r; asm("mov.b64 %0,{%1,%2};" : "=l"(r) : "f"(lo), "f"(hi)); return r;
}
__device__ __forceinline__ float2 unpack2(u64 v) {
    float2 f; asm("mov.b64 {%0,%1},%2;" : "=f"(f.x), "=f"(f.y) : "l"(v)); return f;
}
__device__ __forceinline__ u64 ffma2(u64 a, u64 b, u64 c) {
    u64 d; asm("fma.rn.f32x2 %0,%1,%2,%3;" : "=l"(d) : "l"(a), "l"(b), "l"(c)); return d;
}
__device__ __forceinline__ u64 h2f2p(unsigned u) {
    __half2 h = *reinterpret_cast<__half2*>(&u);
    float2 f = __half22float2(h);
    return pack2(f.x, f.y);
}

// ---------------- mma.sync m16n8k16 helper (tensor pipe) ----------------
__device__ __forceinline__ void mma16816(float& c0, float& c1, float& c2, float& c3,
                                         uint32_t a0, uint32_t a1, uint32_t a2, uint32_t a3,
                                         uint32_t b0, uint32_t b1) {
    asm volatile(
        "mma.sync.aligned.m16n8k16.row.col.f32.f16.f16.f32 "
        "{%0,%1,%2,%3}, {%4,%5,%6,%7}, {%8,%9}, {%0,%1,%2,%3};"
        : "+f"(c0), "+f"(c1), "+f"(c2), "+f"(c3)
        : "r"(a0), "r"(a1), "r"(a2), "r"(a3), "r"(b0), "r"(b1));
}
__device__ __forceinline__ uint32_t packrelu(float x, float y, float bx, float by) {
    __half2 h = __floats2half2_rn(fmaxf(x + bx, 0.0f), fmaxf(y + by, 0.0f));
    return *reinterpret_cast<uint32_t*>(&h);
}
__device__ __forceinline__ uint32_t lds_u32(const __half* p) {
    return *reinterpret_cast<const uint32_t*>(p);
}

// ---------------------------------------------------------------------------
// Kernel 1: transpose (S,Vin,C,D,H,W) fp32 -> (S*Vin,D,H,W,C) fp16, x(1/3)
// (verified: ~52-54us @ ~72% DRAM, at traffic floor)
// ---------------------------------------------------------------------------
__global__ void transpose_kernel(const float* __restrict__ enc) {
    int vox = blockIdx.x * blockDim.x + threadIdx.x;
    if (vox >= kNVox) return;
    int sv = vox / kDHW;
    int p  = vox - sv * kDHW;
    const float* src = enc + sv * (kC * kDHW) + p;
    const float third = 1.0f / 3.0f;
    unsigned h[8];
#pragma unroll
    for (int i = 0; i < 8; i++) {
        float a = src[(2 * i) * kDHW] * third;
        float b = src[(2 * i + 1) * kDHW] * third;
        __half2 hh = __floats2half2_rn(a, b);
        h[i] = *reinterpret_cast<unsigned*>(&hh);
    }
    uint4* dst = reinterpret_cast<uint4*>(g_encT + (size_t)vox * kC);
    dst[0] = make_uint4(h[0], h[1], h[2], h[3]);
    dst[1] = make_uint4(h[4], h[5], h[6], h[7]);
}

// ---------------------------------------------------------------------------
// Kernel 2: persistent render. Grid = 444 CTAs (3/SM); each loops over
// ray-tiles (4 rays x 64 samples per tile). Weights staged ONCE per CTA.
// MLP via mma.sync m16n8k16 (R12-verified).
// ---------------------------------------------------------------------------
__global__ __launch_bounds__(256, 3) void render_kernel(
    const float* __restrict__ tposes,
    const float* __restrict__ iposes,
    const float* __restrict__ fp,
    const float* __restrict__ znp,
    const float* __restrict__ zfp,
    const float* __restrict__ W1, const float* __restrict__ b1,
    const float* __restrict__ W2, const float* __restrict__ b2,
    const float* __restrict__ W3, const float* __restrict__ b3)
{
    __shared__ __half sW1t[64][24];        // [n=j][k=c], stride 24 halves
    __shared__ __half sW2t[64][72];        // [n=j][k],   stride 72 halves
    __shared__ __half sW3t[24][72];        // [n=m][k=j], rows 17..23 zero
    __shared__ __align__(8) float sB1[64];
    __shared__ __align__(8) float sB2[64];
    __shared__ float sB3[17];
    __shared__ __align__(16) __half sFeat[8][32][16];   // [warp][sample][c]
    __shared__ float sOut[8][32][24];      // [warp][sample][m] (17 used, 24 padded)
    __shared__ float sWS[4][2];
    __shared__ float sRed[4][2][16];

    const int tid  = threadIdx.x;
    const int warp = tid >> 5;
    const int lane = tid & 31;

    // ---- stage weights ONCE per persistent CTA ----
    for (int i = tid; i < 24 * 36; i += 256)   // zero W3 tile (24*72 halves)
        reinterpret_cast<uint32_t*>(&sW3t[0][0])[i] = 0;
    __syncthreads();
    for (int i = tid; i < 1024; i += 256) {    // W1t[j][c] = W1[c][j]
        int j = i >> 4, c = i & 15;
        sW1t[j][c] = __float2half(W1[c * 64 + j]);
    }
    for (int i = tid; i < 4096; i += 256) {    // W2t[j][k] = W2[k][j]
        int j = i >> 6, k = i & 63;
        sW2t[j][k] = __float2half(W2[k * 64 + j]);
    }
    for (int i = tid; i < 1088; i += 256) {    // W3t[m][j] = W3[j][m]
        int m = i >> 6, j = i & 63;
        sW3t[m][j] = __float2half(W3[j * 17 + m]);
    }
    if (tid < 64) { sB1[tid] = b1[tid]; sB2[tid] = b2[tid]; }
    if (tid < 17) sB3[tid] = b3[tid];
    __syncthreads();

    const int rb = tid >> 6;          // ray within tile (0..3)
    const int rt = tid & 63;          // sample index along ray
    const int wr = rt >> 5;           // warp within ray (0/1)
    const int slane = rt & 31;

    const float focal = *fp;
    const float zn = *znp, zf = *zfp;
    const float minz = focal * zn;
    const float maxz = focal * zf;
    const float wdscale = 2.0f / (maxz - minz);

    const int r = lane >> 2;          // fragment row group 0..7
    const int q = lane & 3;           // fragment col group 0..3
    const int k0 = 2 * q;             // low k index (halves)

    for (int tile = blockIdx.x; tile < kTiles; tile += kPersistCTAs) {

        const int ray = tile * 4 + rb;
        const int sv  = ray / (kHlo * kWlo);
        const int pix = ray - sv * (kHlo * kWlo);
        const int py  = pix / kWlo;
        const int px  = pix - py * kWlo;
        const int s   = sv / kVt;

        const float* P = tposes + sv * 16;
        const float dcx = ((((float)px + 0.5f) / kWlo) * 2.0f - 1.0f) / focal;
        const float dcy = -(((((float)py + 0.5f) / kHlo) * 2.0f - 1.0f) / focal);
        const float dirx = P[0] * dcx + P[1] * dcy - P[2];
        const float diry = P[4] * dcx + P[5] * dcy - P[6];
        const float dirz = P[8] * dcx + P[9] * dcy - P[10];

        const float t = zn + (zf - zn) * ((float)rt / 63.0f);
        const float ptx = P[3] + t * dirx;
        const float pty = P[7] + t * diry;
        const float ptz = P[11] + t * dirz;

        // --- 3-view trilinear gather (channel-last fp16), branch-free ---
        u64 fa[8];
#pragma unroll
        for (int qq = 0; qq < 8; qq++) fa[qq] = 0ull;

#pragma unroll
        for (int v = 0; v < kVin; v++) {
            const float* IP = iposes + (s * kVin + v) * 16;
            const float dx = ptx - IP[3];
            const float dy = pty - IP[7];
            const float dz = ptz - IP[11];
            const float lx = IP[0] * dx + IP[4] * dy + IP[8]  * dz;
            const float ly = IP[1] * dx + IP[5] * dy + IP[9]  * dz;
            const float lz = IP[2] * dx + IP[6] * dy + IP[10] * dz;
            const float z  = -lz;
            const float invz = focal / z;
            const float gx = lx * invz;
            const float gy = -(ly * invz);
            const float gz = -((z - minz) * wdscale - 1.0f);

            const float ixf = (gx + 1.0f) * (0.5f * kW) - 0.5f;
            const float iyf = (gy + 1.0f) * (0.5f * kH) - 0.5f;
            const float izf = (gz + 1.0f) * (0.5f * kD) - 0.5f;

            const float xf0 = floorf(ixf), yf0 = floorf(iyf), zf0 = floorf(izf);
            const int ix0 = (int)xf0, iy0 = (int)yf0, iz0 = (int)zf0;
            const int ix1 = ix0 + 1, iy1 = iy0 + 1, iz1 = iz0 + 1;
            const float fx = ixf - xf0, fy = iyf - yf0, fz = izf - zf0;

            const float wx0 = (ix0 >= 0 && ix0 < kW) ? (1.0f - fx) : 0.0f;
            const float wx1 = (ix1 >= 0 && ix1 < kW) ? fx : 0.0f;
            const float wy0 = (iy0 >= 0 && iy0 < kH) ? (1.0f - fy) : 0.0f;
            const float wy1 = (iy1 >= 0 && iy1 < kH) ? fy : 0.0f;
            const float wz0 = (iz0 >= 0 && iz0 < kD) ? (1.0f - fz) : 0.0f;
            const float wz1 = (iz1 >= 0 && iz1 < kD) ? fz : 0.0f;
            const int xi0 = min(max(ix0, 0), kW - 1);
            const int xi1 = min(max(ix1, 0), kW - 1);
            const int yi0 = min(max(iy0, 0), kH - 1);
            const int yi1 = min(max(iy1, 0), kH - 1);
            const int zi0 = min(max(iz0, 0), kD - 1);
            const int zi1 = min(max(iz1, 0), kD - 1);

            const int svin = s * kVin + v;
            const int rowb[4] = {
                ((svin * kD + zi0) * kH + yi0) * kW,
                ((svin * kD + zi0) * kH + yi1) * kW,
                ((svin * kD + zi1) * kH + yi0) * kW,
                ((svin * kD + zi1) * kH + yi1) * kW };
            const float wzy[4] = { wz0 * wy0, wz0 * wy1, wz1 * wy0, wz1 * wy1 };

#pragma unroll
            for (int e = 0; e < 4; e++) {
                const uint4* p0 = reinterpret_cast<const uint4*>(
                    g_encT + (size_t)(rowb[e] + xi0) * kC);
                const uint4* p1 = reinterpret_cast<const uint4*>(
                    g_encT + (size_t)(rowb[e] + xi1) * kC);
                uint4 a0 = p0[0], a1 = p0[1];
                uint4 b0 = p1[0], b1 = p1[1];
                const float w0s = wzy[e] * wx0;
                const float w1s = wzy[e] * wx1;
                const u64 w0 = pack2(w0s, w0s);
                const u64 w1 = pack2(w1s, w1s);
                fa[0] = ffma2(w0, h2f2p(a0.x), fa[0]);
                fa[1] = ffma2(w0, h2f2p(a0.y), fa[1]);
                fa[2] = ffma2(w0, h2f2p(a0.z), fa[2]);
                fa[3] = ffma2(w0, h2f2p(a0.w), fa[3]);
                fa[4] = ffma2(w0, h2f2p(a1.x), fa[4]);
                fa[5] = ffma2(w0, h2f2p(a1.y), fa[5]);
                fa[6] = ffma2(w0, h2f2p(a1.z), fa[6]);
                fa[7] = ffma2(w0, h2f2p(a1.w), fa[7]);
                fa[0] = ffma2(w1, h2f2p(b0.x), fa[0]);
                fa[1] = ffma2(w1, h2f2p(b0.y), fa[1]);
                fa[2] = ffma2(w1, h2f2p(b0.z), fa[2]);
                fa[3] = ffma2(w1, h2f2p(b0.w), fa[3]);
                fa[4] = ffma2(w1, h2f2p(b1.x), fa[4]);
                fa[5] = ffma2(w1, h2f2p(b1.y), fa[5]);
                fa[6] = ffma2(w1, h2f2p(b1.z), fa[6]);
                fa[7] = ffma2(w1, h2f2p(b1.w), fa[7]);
            }
        }

        // --- stage feats (fp16) into per-warp shared tile [sample][c] ---
        {
            uint32_t h2w[8];
#pragma unroll
            for (int qq = 0; qq < 8; qq++) {
                float2 f = unpack2(fa[qq]);
                __half2 hh = __floats2half2_rn(f.x, f.y);
                h2w[qq] = *reinterpret_cast<uint32_t*>(&hh);
            }
            uint4* dst = reinterpret_cast<uint4*>(&sFeat[warp][lane][0]);
            dst[0] = make_uint4(h2w[0], h2w[1], h2w[2], h2w[3]);
            dst[1] = make_uint4(h2w[4], h2w[5], h2w[6], h2w[7]);
        }
        __syncwarp();

        // ---- A1 fragments (m16k16 x 2 m-tiles) from sFeat ----
        uint32_t A1[2][4];
#pragma unroll
        for (int mt = 0; mt < 2; mt++) {
            const int rowb = mt * 16;
            A1[mt][0] = lds_u32(&sFeat[warp][rowb + r][k0]);
            A1[mt][1] = lds_u32(&sFeat[warp][rowb + r + 8][k0]);
            A1[mt][2] = lds_u32(&sFeat[warp][rowb + r][k0 + 8]);
            A1[mt][3] = lds_u32(&sFeat[warp][rowb + r + 8][k0 + 8]);
        }

        // ---- Layer 1: 16 -> 64 ----
        uint32_t A2[2][4][4];
#pragma unroll
        for (int jp = 0; jp < 4; jp++) {
            float C[2][2][4];
#pragma unroll
            for (int mt = 0; mt < 2; mt++)
#pragma unroll
                for (int jin = 0; jin < 2; jin++)
#pragma unroll
                    for (int e = 0; e < 4; e++) C[mt][jin][e] = 0.0f;
#pragma unroll
            for (int jin = 0; jin < 2; jin++) {
                const int j = 2 * jp + jin;
                const uint32_t b0 = lds_u32(&sW1t[8 * j + r][k0]);
                const uint32_t b1 = lds_u32(&sW1t[8 * j + r][k0 + 8]);
#pragma unroll
                for (int mt = 0; mt < 2; mt++)
                    mma16816(C[mt][jin][0], C[mt][jin][1], C[mt][jin][2], C[mt][jin][3],
                             A1[mt][0], A1[mt][1], A1[mt][2], A1[mt][3], b0, b1);
            }
            const float2 bA = *reinterpret_cast<const float2*>(&sB1[16 * jp + k0]);
            const float2 bB = *reinterpret_cast<const float2*>(&sB1[16 * jp + 8 + k0]);
#pragma unroll
            for (int mt = 0; mt < 2; mt++) {
                A2[mt][jp][0] = packrelu(C[mt][0][0], C[mt][0][1], bA.x, bA.y);
                A2[mt][jp][1] = packrelu(C[mt][0][2], C[mt][0][3], bA.x, bA.y);
                A2[mt][jp][2] = packrelu(C[mt][1][0], C[mt][1][1], bB.x, bB.y);
                A2[mt][jp][3] = packrelu(C[mt][1][2], C[mt][1][3], bB.x, bB.y);
            }
        }

        // ---- Layer 2: 64 -> 64 ----
        uint32_t A3[2][4][4];
#pragma unroll
        for (int jp = 0; jp < 4; jp++) {
            float C[2][2][4];
#pragma unroll
            for (int mt = 0; mt < 2; mt++)
#pragma unroll
                for (int jin = 0; jin < 2; jin++)
#pragma unroll
                    for (int e = 0; e < 4; e++) C[mt][jin][e] = 0.0f;
#pragma unroll
            for (int jin = 0; jin < 2; jin++) {
                const int j = 2 * jp + jin;
#pragma unroll
                for (int kk = 0; kk < 4; kk++) {
                    const uint32_t b0 = lds_u32(&sW2t[8 * j + r][16 * kk + k0]);
                    const uint32_t b1 = lds_u32(&sW2t[8 * j + r][16 * kk + k0 + 8]);
#pragma unroll
                    for (int mt = 0; mt < 2; mt++)
                        mma16816(C[mt][jin][0], C[mt][jin][1], C[mt][jin][2], C[mt][jin][3],
                                 A2[mt][kk][0], A2[mt][kk][1], A2[mt][kk][2], A2[mt][kk][3],
                                 b0, b1);
                }
            }
            const float2 bA = *reinterpret_cast<const float2*>(&sB2[16 * jp + k0]);
            const float2 bB = *reinterpret_cast<const float2*>(&sB2[16 * jp + 8 + k0]);
#pragma unroll
            for (int mt = 0; mt < 2; mt++) {
                A3[mt][jp][0] = packrelu(C[mt][0][0], C[mt][0][1], bA.x, bA.y);
                A3[mt][jp][1] = packrelu(C[mt][0][2], C[mt][0][3], bA.x, bA.y);
                A3[mt][jp][2] = packrelu(C[mt][1][0], C[mt][1][1], bB.x, bB.y);
                A3[mt][jp][3] = packrelu(C[mt][1][2], C[mt][1][3], bB.x, bB.y);
            }
        }

        // ---- Layer 3: 64 -> 17 (3 n-tiles, padded to 24) ----
#pragma unroll
        for (int j = 0; j < 3; j++) {
            float C[2][4];
#pragma unroll
            for (int mt = 0; mt < 2; mt++)
#pragma unroll
                for (int e = 0; e < 4; e++) C[mt][e] = 0.0f;
#pragma unroll
            for (int kk = 0; kk < 4; kk++) {
                const uint32_t b0 = lds_u32(&sW3t[8 * j + r][16 * kk + k0]);
                const uint32_t b1 = lds_u32(&sW3t[8 * j + r][16 * kk + k0 + 8]);
#pragma unroll
                for (int mt = 0; mt < 2; mt++)
                    mma16816(C[mt][0], C[mt][1], C[mt][2], C[mt][3],
                             A3[mt][kk][0], A3[mt][kk][1], A3[mt][kk][2], A3[mt][kk][3],
                             b0, b1);
            }
            const int col = 8 * j + k0;
#pragma unroll
            for (int mt = 0; mt < 2; mt++) {
                const int row0 = mt * 16 + r;
                sOut[warp][row0][col]     = C[mt][0];
                sOut[warp][row0][col + 1] = C[mt][1];
                sOut[warp][row0 + 8][col]     = C[mt][2];
                sOut[warp][row0 + 8][col + 1] = C[mt][3];
            }
        }
        __syncwarp();

        // ---- per-sample outputs ----
        float o[17];
#pragma unroll
        for (int m = 0; m < 17; m++)
            o[m] = sOut[warp][lane][m] + sB3[m];

        // feats from live fa registers (volume pre-scaled by 1/3)
        float feats[16];
#pragma unroll
        for (int qq = 0; qq < 8; qq++) {
            float2 ff = unpack2(fa[qq]);
            feats[2 * qq] = ff.x; feats[2 * qq + 1] = ff.y;
        }

        const float density = fmaxf(o[0], 0.0f);
        const float delta = (rt == 63) ? 1e10f : (zf - zn) * (1.0f / 63.0f);
        const float sd = density * delta;

        // Inclusive scan of sd across the 64 threads of this ray
        float vscan = sd;
#pragma unroll
        for (int off = 1; off < 32; off <<= 1) {
            float n = __shfl_up_sync(0xffffffffu, vscan, off);
            if (slane >= off) vscan += n;
        }
        if (slane == 31) sWS[rb][wr] = vscan;
        __syncthreads();
        const float cum = vscan + ((wr == 1) ? sWS[rb][0] : 0.0f);
        const float T = __expf(-cum);
        const float alpha = 1.0f - __expf(-sd);
        const float wgt = alpha * T;

#pragma unroll
        for (int c = 0; c < 16; c++) {
            float val = wgt * (feats[c] + o[c + 1]);
#pragma unroll
            for (int off = 16; off > 0; off >>= 1)
                val += __shfl_down_sync(0xffffffffu, val, off);
            if (slane == 0) sRed[rb][wr][c] = val;
        }
        __syncthreads();
        if (rt < 16) {
            g_rlo[((sv * kC + rt) * kHlo + py) * kWlo + px] =
                sRed[rb][0][rt] + sRed[rb][1][rt];
        }
        __syncthreads();   // protect sWS/sRed/sFeat/sOut reuse next iteration
    }
}

// ---------------------------------------------------------------------------
// Kernel 3: 2x bilinear upsample, align_corners=True (48 -> 96), float4 out
// ---------------------------------------------------------------------------
__global__ void upsample_kernel(float* __restrict__ out) {
    const int n4 = blockIdx.x * blockDim.x + threadIdx.x;
    constexpr int kTot4 = kS * kVt * kC * kH * kW / 4;
    if (n4 >= kTot4) return;
    const int xq  = n4 % (kW / 4);        // group of 4 x
    const int y   = (n4 / (kW / 4)) % kH;
    const int svc = n4 / (kH * kW / 4);

    const float pyf = (float)y * (47.0f / 95.0f);
    const int ly = (int)pyf; const int hy = min(ly + 1, 47);
    const float fy = pyf - (float)ly;

    const float* rlo = g_rlo + svc * (kHlo * kWlo);
    const float* r0 = rlo + ly * kWlo;
    const float* r1 = rlo + hy * kWlo;

    float res[4];
#pragma unroll
    for (int i = 0; i < 4; i++) {
        const int x = xq * 4 + i;
        const float pxf = (float)x * (47.0f / 95.0f);
        const int lx = (int)pxf; const int hx = min(lx + 1, 47);
        const float fx = pxf - (float)lx;
        const float v0 = r0[lx] * (1.0f - fx) + r0[hx] * fx;
        const float v1 = r1[lx] * (1.0f - fx) + r1[hx] * fx;
        res[i] = v0 * (1.0f - fy) + v1 * fy;
    }
    reinterpret_cast<float4*>(out)[n4] =
        make_float4(res[0], res[1], res[2], res[3]);
}

// ---------------------------------------------------------------------------
extern "C" void kernel_launch(void* const* d_in, const int* in_sizes, int n_in,
                              void* d_out, int out_size) {
    const float* enc = (const float*)d_in[0];
    const float* ipo = (const float*)d_in[1];
    const float* tpo = (const float*)d_in[2];
    const float* fp  = (const float*)d_in[3];
    const float* znp = (const float*)d_in[4];
    const float* zfp = (const float*)d_in[5];
    const float* W1 = (const float*)d_in[7];
    const float* b1 = (const float*)d_in[8];
    const float* W2 = (const float*)d_in[9];
    const float* b2 = (const float*)d_in[10];
    const float* W3 = (const float*)d_in[11];
    const float* b3 = (const float*)d_in[12];
    float* out = (float*)d_out;

    transpose_kernel<<<(kNVox + 255) / 256, 256>>>(enc);
    render_kernel<<<kPersistCTAs, 256>>>(tpo, ipo, fp, znp, zfp,
                                         W1, b1, W2, b2, W3, b3);
    constexpr int kTot4 = kS * kVt * kC * kH * kW / 4;
    upsample_kernel<<<(kTot4 + 255) / 256, 256>>>(out);
}

// round 16
// speedup vs baseline: 1.7506x; 1.0549x over previous
#include <cuda_runtime.h>
#include <cuda_fp16.h>
#include <cstdint>

// Static problem shapes (from setup_inputs)
constexpr int kS   = 2;
constexpr int kVin = 3;
constexpr int kVt  = 4;
constexpr int kC   = 16;
constexpr int kD   = 64;
constexpr int kH   = 96;
constexpr int kW   = 96;
constexpr int kHlo = 48;
constexpr int kWlo = 48;

constexpr int kDHW  = kD * kH * kW;           // 589824
constexpr int kNVox = kS * kVin * kDHW;       // 3,538,944
constexpr int kRays = kS * kVt * kHlo * kWlo; // 18432
constexpr int kTiles = kRays / 4;             // 4608 ray-groups
constexpr int kPersistCTAs = 444;             // 3 per SM x 148 SMs

// Scratch: channel-last fp16 volume (113 MB), pre-scaled by 1/3
__device__ __half g_encT[(size_t)kNVox * kC];
__device__ float  g_rlo[kS * kVt * kC * kHlo * kWlo];
__device__ int    g_ticket;                    // dynamic tile ticket

// ---------------- packed f32x2 helpers (sm_103a) ----------------
using u64 = unsigned long long;
__device__ __forceinline__ u64 pack2(float lo, float hi) {
    u64 r; asm("mov.b64 %0,{%1,%2};" : "=l"(r) : "f"(lo), "f"(hi)); return r;
}
__device__ __forceinline__ float2 unpack2(u64 v) {
    float2 f; asm("mov.b64 {%0,%1},%2;" : "=f"(f.x), "=f"(f.y) : "l"(v)); return f;
}
__device__ __forceinline__ u64 ffma2(u64 a, u64 b, u64 c) {
    u64 d; asm("fma.rn.f32x2 %0,%1,%2,%3;" : "=l"(d) : "l"(a), "l"(b), "l"(c)); return d;
}
__device__ __forceinline__ u64 h2f2p(unsigned u) {
    __half2 h = *reinterpret_cast<__half2*>(&u);
    float2 f = __half22float2(h);
    return pack2(f.x, f.y);
}

// ---------------- mma.sync m16n8k16 helper (tensor pipe) ----------------
__device__ __forceinline__ void mma16816(float& c0, float& c1, float& c2, float& c3,
                                         uint32_t a0, uint32_t a1, uint32_t a2, uint32_t a3,
                                         uint32_t b0, uint32_t b1) {
    asm volatile(
        "mma.sync.aligned.m16n8k16.row.col.f32.f16.f16.f32 "
        "{%0,%1,%2,%3}, {%4,%5,%6,%7}, {%8,%9}, {%0,%1,%2,%3};"
        : "+f"(c0), "+f"(c1), "+f"(c2), "+f"(c3)
        : "r"(a0), "r"(a1), "r"(a2), "r"(a3), "r"(b0), "r"(b1));
}
__device__ __forceinline__ uint32_t packrelu(float x, float y, float bx, float by) {
    __half2 h = __floats2half2_rn(fmaxf(x + bx, 0.0f), fmaxf(y + by, 0.0f));
    return *reinterpret_cast<uint32_t*>(&h);
}
__device__ __forceinline__ uint32_t lds_u32(const __half* p) {
    return *reinterpret_cast<const uint32_t*>(p);
}

// ---------------------------------------------------------------------------
// Kernel 1: transpose (S,Vin,C,D,H,W) fp32 -> (S*Vin,D,H,W,C) fp16, x(1/3)
// Streaming reads (__ldcs): fp32 source is read-once; keep writes in L2.
// Also resets the render tile ticket.
// ---------------------------------------------------------------------------
__global__ void transpose_kernel(const float* __restrict__ enc) {
    if (blockIdx.x == 0 && threadIdx.x == 0) g_ticket = 0;
    int vox = blockIdx.x * blockDim.x + threadIdx.x;
    if (vox >= kNVox) return;
    int sv = vox / kDHW;
    int p  = vox - sv * kDHW;
    const float* src = enc + sv * (kC * kDHW) + p;
    const float third = 1.0f / 3.0f;
    unsigned h[8];
#pragma unroll
    for (int i = 0; i < 8; i++) {
        float a = __ldcs(&src[(2 * i) * kDHW]) * third;
        float b = __ldcs(&src[(2 * i + 1) * kDHW]) * third;
        __half2 hh = __floats2half2_rn(a, b);
        h[i] = *reinterpret_cast<unsigned*>(&hh);
    }
    uint4* dst = reinterpret_cast<uint4*>(g_encT + (size_t)vox * kC);
    dst[0] = make_uint4(h[0], h[1], h[2], h[3]);
    dst[1] = make_uint4(h[4], h[5], h[6], h[7]);
}

// ---------------------------------------------------------------------------
// Kernel 2: persistent render, dynamic ticketing. Grid = 444 CTAs (3/SM).
// Tile = 4 rays x 64 samples. Weights staged once. MLP via mma.sync.
// ---------------------------------------------------------------------------
__global__ __launch_bounds__(256, 3) void render_kernel(
    const float* __restrict__ tposes,
    const float* __restrict__ iposes,
    const float* __restrict__ fp,
    const float* __restrict__ znp,
    const float* __restrict__ zfp,
    const float* __restrict__ W1, const float* __restrict__ b1,
    const float* __restrict__ W2, const float* __restrict__ b2,
    const float* __restrict__ W3, const float* __restrict__ b3)
{
    __shared__ __half sW1t[64][24];        // [n=j][k=c], stride 24 halves
    __shared__ __half sW2t[64][72];        // [n=j][k],   stride 72 halves
    __shared__ __half sW3t[24][72];        // [n=m][k=j], rows 17..23 zero
    __shared__ __align__(8) float sB1[64];
    __shared__ __align__(8) float sB2[64];
    __shared__ float sB3[17];
    __shared__ __align__(16) __half sFeat[8][32][16];   // [warp][sample][c]
    __shared__ float sOut[8][32][24];      // [warp][sample][m] (17 used, 24 padded)
    __shared__ float sWS[4][2];
    __shared__ float sRed[4][2][16];
    __shared__ int   sTile;

    const int tid  = threadIdx.x;
    const int warp = tid >> 5;
    const int lane = tid & 31;

    // ---- stage weights ONCE per persistent CTA ----
    for (int i = tid; i < 24 * 36; i += 256)   // zero W3 tile (24*72 halves)
        reinterpret_cast<uint32_t*>(&sW3t[0][0])[i] = 0;
    __syncthreads();
    for (int i = tid; i < 1024; i += 256) {    // W1t[j][c] = W1[c][j]
        int j = i >> 4, c = i & 15;
        sW1t[j][c] = __float2half(W1[c * 64 + j]);
    }
    for (int i = tid; i < 4096; i += 256) {    // W2t[j][k] = W2[k][j]
        int j = i >> 6, k = i & 63;
        sW2t[j][k] = __float2half(W2[k * 64 + j]);
    }
    for (int i = tid; i < 1088; i += 256) {    // W3t[m][j] = W3[j][m]
        int m = i >> 6, j = i & 63;
        sW3t[m][j] = __float2half(W3[j * 17 + m]);
    }
    if (tid < 64) { sB1[tid] = b1[tid]; sB2[tid] = b2[tid]; }
    if (tid < 17) sB3[tid] = b3[tid];

    const int rb = tid >> 6;          // ray within tile (0..3)
    const int rt = tid & 63;          // sample index along ray
    const int wr = rt >> 5;           // warp within ray (0/1)
    const int slane = rt & 31;

    const float focal = *fp;
    const float zn = *znp, zf = *zfp;
    const float minz = focal * zn;
    const float maxz = focal * zf;
    const float wdscale = 2.0f / (maxz - minz);

    const int r = lane >> 2;          // fragment row group 0..7
    const int q = lane & 3;           // fragment col group 0..3
    const int k0 = 2 * q;             // low k index (halves)

    for (;;) {
        // Dynamic ticket: doubles as the barrier protecting shared reuse.
        if (tid == 0) sTile = atomicAdd(&g_ticket, 1);
        __syncthreads();
        const int tile = sTile;
        if (tile >= kTiles) break;

        const int ray = tile * 4 + rb;
        const int sv  = ray / (kHlo * kWlo);
        const int pix = ray - sv * (kHlo * kWlo);
        const int py  = pix / kWlo;
        const int px  = pix - py * kWlo;
        const int s   = sv / kVt;

        const float* P = tposes + sv * 16;
        const float dcx = ((((float)px + 0.5f) / kWlo) * 2.0f - 1.0f) / focal;
        const float dcy = -(((((float)py + 0.5f) / kHlo) * 2.0f - 1.0f) / focal);
        const float dirx = P[0] * dcx + P[1] * dcy - P[2];
        const float diry = P[4] * dcx + P[5] * dcy - P[6];
        const float dirz = P[8] * dcx + P[9] * dcy - P[10];

        const float t = zn + (zf - zn) * ((float)rt / 63.0f);
        const float ptx = P[3] + t * dirx;
        const float pty = P[7] + t * diry;
        const float ptz = P[11] + t * dirz;

        // --- 3-view trilinear gather (channel-last fp16), branch-free ---
        u64 fa[8];
#pragma unroll
        for (int qq = 0; qq < 8; qq++) fa[qq] = 0ull;

#pragma unroll
        for (int v = 0; v < kVin; v++) {
            const float* IP = iposes + (s * kVin + v) * 16;
            const float dx = ptx - IP[3];
            const float dy = pty - IP[7];
            const float dz = ptz - IP[11];
            const float lx = IP[0] * dx + IP[4] * dy + IP[8]  * dz;
            const float ly = IP[1] * dx + IP[5] * dy + IP[9]  * dz;
            const float lz = IP[2] * dx + IP[6] * dy + IP[10] * dz;
            const float z  = -lz;
            const float invz = focal / z;
            const float gx = lx * invz;
            const float gy = -(ly * invz);
            const float gz = -((z - minz) * wdscale - 1.0f);

            const float ixf = (gx + 1.0f) * (0.5f * kW) - 0.5f;
            const float iyf = (gy + 1.0f) * (0.5f * kH) - 0.5f;
            const float izf = (gz + 1.0f) * (0.5f * kD) - 0.5f;

            const float xf0 = floorf(ixf), yf0 = floorf(iyf), zf0 = floorf(izf);
            const int ix0 = (int)xf0, iy0 = (int)yf0, iz0 = (int)zf0;
            const int ix1 = ix0 + 1, iy1 = iy0 + 1, iz1 = iz0 + 1;
            const float fx = ixf - xf0, fy = iyf - yf0, fz = izf - zf0;

            const float wx0 = (ix0 >= 0 && ix0 < kW) ? (1.0f - fx) : 0.0f;
            const float wx1 = (ix1 >= 0 && ix1 < kW) ? fx : 0.0f;
            const float wy0 = (iy0 >= 0 && iy0 < kH) ? (1.0f - fy) : 0.0f;
            const float wy1 = (iy1 >= 0 && iy1 < kH) ? fy : 0.0f;
            const float wz0 = (iz0 >= 0 && iz0 < kD) ? (1.0f - fz) : 0.0f;
            const float wz1 = (iz1 >= 0 && iz1 < kD) ? fz : 0.0f;
            const int xi0 = min(max(ix0, 0), kW - 1);
            const int xi1 = min(max(ix1, 0), kW - 1);
            const int yi0 = min(max(iy0, 0), kH - 1);
            const int yi1 = min(max(iy1, 0), kH - 1);
            const int zi0 = min(max(iz0, 0), kD - 1);
            const int zi1 = min(max(iz1, 0), kD - 1);

            const int svin = s * kVin + v;
            const int rowb[4] = {
                ((svin * kD + zi0) * kH + yi0) * kW,
                ((svin * kD + zi0) * kH + yi1) * kW,
                ((svin * kD + zi1) * kH + yi0) * kW,
                ((svin * kD + zi1) * kH + yi1) * kW };
            const float wzy[4] = { wz0 * wy0, wz0 * wy1, wz1 * wy0, wz1 * wy1 };

#pragma unroll
            for (int e = 0; e < 4; e++) {
                const uint4* p0 = reinterpret_cast<const uint4*>(
                    g_encT + (size_t)(rowb[e] + xi0) * kC);
                const uint4* p1 = reinterpret_cast<const uint4*>(
                    g_encT + (size_t)(rowb[e] + xi1) * kC);
                uint4 a0 = p0[0], a1 = p0[1];
                uint4 b0 = p1[0], b1 = p1[1];
                const float w0s = wzy[e] * wx0;
                const float w1s = wzy[e] * wx1;
                const u64 w0 = pack2(w0s, w0s);
                const u64 w1 = pack2(w1s, w1s);
                fa[0] = ffma2(w0, h2f2p(a0.x), fa[0]);
                fa[1] = ffma2(w0, h2f2p(a0.y), fa[1]);
                fa[2] = ffma2(w0, h2f2p(a0.z), fa[2]);
                fa[3] = ffma2(w0, h2f2p(a0.w), fa[3]);
                fa[4] = ffma2(w0, h2f2p(a1.x), fa[4]);
                fa[5] = ffma2(w0, h2f2p(a1.y), fa[5]);
                fa[6] = ffma2(w0, h2f2p(a1.z), fa[6]);
                fa[7] = ffma2(w0, h2f2p(a1.w), fa[7]);
                fa[0] = ffma2(w1, h2f2p(b0.x), fa[0]);
                fa[1] = ffma2(w1, h2f2p(b0.y), fa[1]);
                fa[2] = ffma2(w1, h2f2p(b0.z), fa[2]);
                fa[3] = ffma2(w1, h2f2p(b0.w), fa[3]);
                fa[4] = ffma2(w1, h2f2p(b1.x), fa[4]);
                fa[5] = ffma2(w1, h2f2p(b1.y), fa[5]);
                fa[6] = ffma2(w1, h2f2p(b1.z), fa[6]);
                fa[7] = ffma2(w1, h2f2p(b1.w), fa[7]);
            }
        }

        // --- stage feats (fp16) into per-warp shared tile [sample][c] ---
        {
            uint32_t h2w[8];
#pragma unroll
            for (int qq = 0; qq < 8; qq++) {
                float2 f = unpack2(fa[qq]);
                __half2 hh = __floats2half2_rn(f.x, f.y);
                h2w[qq] = *reinterpret_cast<uint32_t*>(&hh);
            }
            uint4* dst = reinterpret_cast<uint4*>(&sFeat[warp][lane][0]);
            dst[0] = make_uint4(h2w[0], h2w[1], h2w[2], h2w[3]);
            dst[1] = make_uint4(h2w[4], h2w[5], h2w[6], h2w[7]);
        }
        __syncwarp();

        // ---- A1 fragments (m16k16 x 2 m-tiles) from sFeat ----
        uint32_t A1[2][4];
#pragma unroll
        for (int mt = 0; mt < 2; mt++) {
            const int rowb = mt * 16;
            A1[mt][0] = lds_u32(&sFeat[warp][rowb + r][k0]);
            A1[mt][1] = lds_u32(&sFeat[warp][rowb + r + 8][k0]);
            A1[mt][2] = lds_u32(&sFeat[warp][rowb + r][k0 + 8]);
            A1[mt][3] = lds_u32(&sFeat[warp][rowb + r + 8][k0 + 8]);
        }

        // ---- Layer 1: 16 -> 64 ----
        uint32_t A2[2][4][4];
#pragma unroll
        for (int jp = 0; jp < 4; jp++) {
            float C[2][2][4];
#pragma unroll
            for (int mt = 0; mt < 2; mt++)
#pragma unroll
                for (int jin = 0; jin < 2; jin++)
#pragma unroll
                    for (int e = 0; e < 4; e++) C[mt][jin][e] = 0.0f;
#pragma unroll
            for (int jin = 0; jin < 2; jin++) {
                const int j = 2 * jp + jin;
                const uint32_t b0 = lds_u32(&sW1t[8 * j + r][k0]);
                const uint32_t b1 = lds_u32(&sW1t[8 * j + r][k0 + 8]);
#pragma unroll
                for (int mt = 0; mt < 2; mt++)
                    mma16816(C[mt][jin][0], C[mt][jin][1], C[mt][jin][2], C[mt][jin][3],
                             A1[mt][0], A1[mt][1], A1[mt][2], A1[mt][3], b0, b1);
            }
            const float2 bA = *reinterpret_cast<const float2*>(&sB1[16 * jp + k0]);
            const float2 bB = *reinterpret_cast<const float2*>(&sB1[16 * jp + 8 + k0]);
#pragma unroll
            for (int mt = 0; mt < 2; mt++) {
                A2[mt][jp][0] = packrelu(C[mt][0][0], C[mt][0][1], bA.x, bA.y);
                A2[mt][jp][1] = packrelu(C[mt][0][2], C[mt][0][3], bA.x, bA.y);
                A2[mt][jp][2] = packrelu(C[mt][1][0], C[mt][1][1], bB.x, bB.y);
                A2[mt][jp][3] = packrelu(C[mt][1][2], C[mt][1][3], bB.x, bB.y);
            }
        }

        // ---- Layer 2: 64 -> 64 ----
        uint32_t A3[2][4][4];
#pragma unroll
        for (int jp = 0; jp < 4; jp++) {
            float C[2][2][4];
#pragma unroll
            for (int mt = 0; mt < 2; mt++)
#pragma unroll
                for (int jin = 0; jin < 2; jin++)
#pragma unroll
                    for (int e = 0; e < 4; e++) C[mt][jin][e] = 0.0f;
#pragma unroll
            for (int jin = 0; jin < 2; jin++) {
                const int j = 2 * jp + jin;
#pragma unroll
                for (int kk = 0; kk < 4; kk++) {
                    const uint32_t b0 = lds_u32(&sW2t[8 * j + r][16 * kk + k0]);
                    const uint32_t b1 = lds_u32(&sW2t[8 * j + r][16 * kk + k0 + 8]);
#pragma unroll
                    for (int mt = 0; mt < 2; mt++)
                        mma16816(C[mt][jin][0], C[mt][jin][1], C[mt][jin][2], C[mt][jin][3],
                                 A2[mt][kk][0], A2[mt][kk][1], A2[mt][kk][2], A2[mt][kk][3],
                                 b0, b1);
                }
            }
            const float2 bA = *reinterpret_cast<const float2*>(&sB2[16 * jp + k0]);
            const float2 bB = *reinterpret_cast<const float2*>(&sB2[16 * jp + 8 + k0]);
#pragma unroll
            for (int mt = 0; mt < 2; mt++) {
                A3[mt][jp][0] = packrelu(C[mt][0][0], C[mt][0][1], bA.x, bA.y);
                A3[mt][jp][1] = packrelu(C[mt][0][2], C[mt][0][3], bA.x, bA.y);
                A3[mt][jp][2] = packrelu(C[mt][1][0], C[mt][1][1], bB.x, bB.y);
                A3[mt][jp][3] = packrelu(C[mt][1][2], C[mt][1][3], bB.x, bB.y);
            }
        }

        // ---- Layer 3: 64 -> 17 (3 n-tiles, padded to 24) ----
#pragma unroll
        for (int j = 0; j < 3; j++) {
            float C[2][4];
#pragma unroll
            for (int mt = 0; mt < 2; mt++)
#pragma unroll
                for (int e = 0; e < 4; e++) C[mt][e] = 0.0f;
#pragma unroll
            for (int kk = 0; kk < 4; kk++) {
                const uint32_t b0 = lds_u32(&sW3t[8 * j + r][16 * kk + k0]);
                const uint32_t b1 = lds_u32(&sW3t[8 * j + r][16 * kk + k0 + 8]);
#pragma unroll
                for (int mt = 0; mt < 2; mt++)
                    mma16816(C[mt][0], C[mt][1], C[mt][2], C[mt][3],
                             A3[mt][kk][0], A3[mt][kk][1], A3[mt][kk][2], A3[mt][kk][3],
                             b0, b1);
            }
            const int col = 8 * j + k0;
#pragma unroll
            for (int mt = 0; mt < 2; mt++) {
                const int row0 = mt * 16 + r;
                sOut[warp][row0][col]     = C[mt][0];
                sOut[warp][row0][col + 1] = C[mt][1];
                sOut[warp][row0 + 8][col]     = C[mt][2];
                sOut[warp][row0 + 8][col + 1] = C[mt][3];
            }
        }
        __syncwarp();

        // ---- per-sample outputs ----
        float o[17];
#pragma unroll
        for (int m = 0; m < 17; m++)
            o[m] = sOut[warp][lane][m] + sB3[m];

        // feats from live fa registers (volume pre-scaled by 1/3)
        float feats[16];
#pragma unroll
        for (int qq = 0; qq < 8; qq++) {
            float2 ff = unpack2(fa[qq]);
            feats[2 * qq] = ff.x; feats[2 * qq + 1] = ff.y;
        }

        const float density = fmaxf(o[0], 0.0f);
        const float delta = (rt == 63) ? 1e10f : (zf - zn) * (1.0f / 63.0f);
        const float sd = density * delta;

        // Inclusive scan of sd across the 64 threads of this ray
        float vscan = sd;
#pragma unroll
        for (int off = 1; off < 32; off <<= 1) {
            float n = __shfl_up_sync(0xffffffffu, vscan, off);
            if (slane >= off) vscan += n;
        }
        if (slane == 31) sWS[rb][wr] = vscan;
        __syncthreads();
        const float cum = vscan + ((wr == 1) ? sWS[rb][0] : 0.0f);
        const float T = __expf(-cum);
        const float alpha = 1.0f - __expf(-sd);
        const float wgt = alpha * T;

#pragma unroll
        for (int c = 0; c < 16; c++) {
            float val = wgt * (feats[c] + o[c + 1]);
#pragma unroll
            for (int off = 16; off > 0; off >>= 1)
                val += __shfl_down_sync(0xffffffffu, val, off);
            if (slane == 0) sRed[rb][wr][c] = val;
        }
        __syncthreads();
        if (rt < 16) {
            g_rlo[((sv * kC + rt) * kHlo + py) * kWlo + px] =
                sRed[rb][0][rt] + sRed[rb][1][rt];
        }
        // next iteration's ticket __syncthreads protects shared reuse
    }
}

// ---------------------------------------------------------------------------
// Kernel 3: 2x bilinear upsample, align_corners=True (48 -> 96), float4 out
// ---------------------------------------------------------------------------
__global__ void upsample_kernel(float* __restrict__ out) {
    const int n4 = blockIdx.x * blockDim.x + threadIdx.x;
    constexpr int kTot4 = kS * kVt * kC * kH * kW / 4;
    if (n4 >= kTot4) return;
    const int xq  = n4 % (kW / 4);        // group of 4 x
    const int y   = (n4 / (kW / 4)) % kH;
    const int svc = n4 / (kH * kW / 4);

    const float pyf = (float)y * (47.0f / 95.0f);
    const int ly = (int)pyf; const int hy = min(ly + 1, 47);
    const float fy = pyf - (float)ly;

    const float* rlo = g_rlo + svc * (kHlo * kWlo);
    const float* r0 = rlo + ly * kWlo;
    const float* r1 = rlo + hy * kWlo;

    float res[4];
#pragma unroll
    for (int i = 0; i < 4; i++) {
        const int x = xq * 4 + i;
        const float pxf = (float)x * (47.0f / 95.0f);
        const int lx = (int)pxf; const int hx = min(lx + 1, 47);
        const float fx = pxf - (float)lx;
        const float v0 = r0[lx] * (1.0f - fx) + r0[hx] * fx;
        const float v1 = r1[lx] * (1.0f - fx) + r1[hx] * fx;
        res[i] = v0 * (1.0f - fy) + v1 * fy;
    }
    reinterpret_cast<float4*>(out)[n4] =
        make_float4(res[0], res[1], res[2], res[3]);
}

// ---------------------------------------------------------------------------
extern "C" void kernel_launch(void* const* d_in, const int* in_sizes, int n_in,
                              void* d_out, int out_size) {
    const float* enc = (const float*)d_in[0];
    const float* ipo = (const float*)d_in[1];
    const float* tpo = (const float*)d_in[2];
    const float* fp  = (const float*)d_in[3];
    const float* znp = (const float*)d_in[4];
    const float* zfp = (const float*)d_in[5];
    const float* W1 = (const float*)d_in[7];
    const float* b1 = (const float*)d_in[8];
    const float* W2 = (const float*)d_in[9];
    const float* b2 = (const float*)d_in[10];
    const float* W3 = (const float*)d_in[11];
    const float* b3 = (const float*)d_in[12];
    float* out = (float*)d_out;

    transpose_kernel<<<(kNVox + 255) / 256, 256>>>(enc);
    render_kernel<<<kPersistCTAs, 256>>>(tpo, ipo, fp, znp, zfp,
                                         W1, b1, W2, b2, W3, b3);
    constexpr int kTot4 = kS * kVt * kC * kH * kW / 4;
    upsample_kernel<<<(kTot4 + 255) / 256, 256>>>(out);
}